// round 13
// baseline (speedup 1.0000x reference)
#include <cuda_runtime.h>
#include <cuda_bf16.h>
#include <cstdint>

// Problem dims (fixed)
#define M_DIM 1024
#define K_DIM 4096
#define N_DIM 4096
#define QBLK  32
#define NKB   (K_DIM / QBLK)      // 128

// GEMM tiling (R12 core): 64x64 CTA, 4 warps of 32x32, STAGES=4, 3 CTAs/SM
#define BM 64
#define BN 64
#define BK 128                    // 128 fp8 = 128B rows (SW128), 4 quant blocks
#define STAGES 4
#define NITER (K_DIM / BK)        // 32
#define THREADS 128
#define NTILES ((M_DIM / BM) * (N_DIM / BN))   // 1024

// Stage smem: A(8K) | B(8K) | sx(1K) | sw(1K)
#define A_OFF   0
#define B_OFF   8192
#define SX_OFF  16384
#define SW_OFF  17408
#define STAGE_B 18432
#define SMEM_TOTAL (STAGES * STAGE_B)   // 73728 -> 3 CTAs/SM

// Quant phase: 320 CTAs, 8 K-ordered chunks (16 quant-blocks of K each)
#define NQ_CTAS 320
#define NFLAGS  8
#define HALVES_PER_CHUNK ((M_DIM + N_DIM) * 16 * 2)   // 163840
#define QTHREADS (NQ_CTAS * THREADS)                  // 40960

// Scratch (device globals)
__device__ uint8_t g_qx[(size_t)M_DIM * K_DIM];   // 4 MB  (e4m3 palette)
__device__ uint8_t g_qw[(size_t)N_DIM * K_DIM];   // 16 MB (e4m3 palette)
__device__ float   g_sx[(size_t)NKB * M_DIM];     // [kb][m] = bm/6
__device__ float   g_sw[(size_t)NKB * N_DIM];     // [kb][n] = bm/6
__device__ int     g_sync[NFLAGS + 1];            // [0..7] chunk flags, [8] tile ctr

// ---------------------------------------------------------------------------
// PTX helpers
// ---------------------------------------------------------------------------
__device__ __forceinline__ uint32_t smem_u32(const void* p) {
    uint32_t a;
    asm("{ .reg .u64 t; cvta.to.shared.u64 t, %1; cvt.u32.u64 %0, t; }"
        : "=r"(a) : "l"(p));
    return a;
}
#define CP_ASYNC16(dst, src) \
    asm volatile("cp.async.cg.shared.global [%0], [%1], 16;" \
                 :: "r"(dst), "l"(src) : "memory")
#define CP_COMMIT() asm volatile("cp.async.commit_group;" ::: "memory")
#define CP_WAIT(n)  asm volatile("cp.async.wait_group %0;" :: "n"(n) : "memory")

#define LDSM4(r0, r1, r2, r3, addr) \
    asm volatile("ldmatrix.sync.aligned.m8n8.x4.shared.b16 {%0,%1,%2,%3}, [%4];" \
                 : "=r"(r0), "=r"(r1), "=r"(r2), "=r"(r3) : "r"(addr))

// fp8 e4m3 MMA, K=32, fp32 accum, C = 0 (exact partial over one quant block)
#define MMA_FP8_Z(d, a, b0, b1) \
    asm volatile("mma.sync.aligned.m16n8k32.row.col.f32.e4m3.e4m3.f32 " \
        "{%0,%1,%2,%3},{%4,%5,%6,%7},{%8,%9},{%10,%10,%10,%10};" \
        : "=f"((d)[0]), "=f"((d)[1]), "=f"((d)[2]), "=f"((d)[3]) \
        : "r"((a)[0]), "r"((a)[1]), "r"((a)[2]), "r"((a)[3]), \
          "r"(b0), "r"(b1), "f"(0.0f))

// packed f32x2 ops
__device__ __forceinline__ unsigned long long pk2(float lo, float hi) {
    unsigned long long d;
    asm("mov.b64 %0, {%1, %2};" : "=l"(d) : "f"(lo), "f"(hi));
    return d;
}
__device__ __forceinline__ unsigned long long pmul2(unsigned long long a,
                                                    unsigned long long b) {
    unsigned long long d;
    asm("mul.rn.f32x2 %0, %1, %2;" : "=l"(d) : "l"(a), "l"(b));
    return d;
}
__device__ __forceinline__ void pfma2(unsigned long long& acc,
                                      unsigned long long a,
                                      unsigned long long b) {
    asm("fma.rn.f32x2 %0, %1, %2, %0;" : "+l"(acc) : "l"(a), "l"(b));
}

__device__ __forceinline__ uint32_t swz128(uint32_t off) {
    return off ^ ((off >> 3) & 0x70);
}

// ---------------------------------------------------------------------------
// Quant math: ceil-based EXACT snap (argmin tie-to-lower preserved) + e4m3 pack
// ---------------------------------------------------------------------------
__device__ __forceinline__ float snap1(float v, float r6) {
    float su = fabsf(v) * r6;
    float pl = ceilf(fmaf(su, 2.0f, -0.5f)) * 0.5f;
    float ph = fminf(ceilf(su - 0.5f), 4.0f);
    float p  = su < 2.0f ? pl : ph;
    p = su > 5.0f ? 6.0f : p;
    return copysignf(p, v);
}
__device__ __forceinline__ uint32_t pack4_e4m3(const float4 v, float r6) {
    uint16_t lo, hi;
    float a0 = snap1(v.x, r6), a1 = snap1(v.y, r6);
    float a2 = snap1(v.z, r6), a3 = snap1(v.w, r6);
    asm("cvt.rn.satfinite.e4m3x2.f32 %0, %1, %2;" : "=h"(lo) : "f"(a1), "f"(a0));
    asm("cvt.rn.satfinite.e4m3x2.f32 %0, %1, %2;" : "=h"(hi) : "f"(a3), "f"(a2));
    return (uint32_t)lo | ((uint32_t)hi << 16);
}

// Quantize 16 elems (one half of a 32-block); partner half is lane^1.
__device__ __forceinline__ void quant16(const float* __restrict__ src,
                                        uint8_t* __restrict__ dst,
                                        float* __restrict__ sdst,
                                        int rows, int row, int kb, int h) {
    const size_t base = (size_t)row * K_DIM + (size_t)kb * QBLK + h * 16;
    float4 v[4];
    #pragma unroll
    for (int i = 0; i < 4; i++) v[i] = *(const float4*)(src + base + i * 4);

    float a = 0.0f;
    #pragma unroll
    for (int i = 0; i < 4; i++)
        a = fmaxf(a, fmaxf(fmaxf(fabsf(v[i].x), fabsf(v[i].y)),
                           fmaxf(fabsf(v[i].z), fabsf(v[i].w))));
    a = fmaxf(a, __shfl_xor_sync(0xffffffffu, a, 1));
    float bm = fmaxf(a, 1e-12f);
    float r6 = 6.0f / bm;

    uint4 pk;
    pk.x = pack4_e4m3(v[0], r6);
    pk.y = pack4_e4m3(v[1], r6);
    pk.z = pack4_e4m3(v[2], r6);
    pk.w = pack4_e4m3(v[3], r6);
    *(uint4*)(dst + base) = pk;

    if (h == 0)
        sdst[(size_t)kb * rows + row] = bm / 6.0f;
}

// ---------------------------------------------------------------------------
// Fused persistent kernel: phase 1 = chunked quant (K-ordered, flagged),
// phase 2 = persistent fp8 block-scaled GEMM with per-stage flag gating.
// ---------------------------------------------------------------------------
__global__ __launch_bounds__(THREADS, 3)
void fused_kernel(const float* __restrict__ x,
                  const float* __restrict__ w,
                  float* __restrict__ C) {
    extern __shared__ __align__(1024) char smem[];
    __shared__ int s_tile;
    const uint32_t sb = smem_u32(smem);
    const int tid  = threadIdx.x;
    const int cta  = blockIdx.x;
    const int narrive = (int)gridDim.x;

    // ================= Phase 1: quantization (CTAs 0..319) =================
    if (cta < NQ_CTAS) {
        const int G = cta * THREADS + tid;
        for (int s = 0; s < NFLAGS; s++) {
            #pragma unroll
            for (int j = 0; j < 4; j++) {
                int T = G + QTHREADS * j;       // 0..163839
                int b = T >> 1, h = T & 1;
                int rowc = b >> 4;              // 0..5119
                int kb   = s * 16 + (b & 15);
                if (rowc < M_DIM)
                    quant16(x, g_qx, g_sx, M_DIM, rowc, kb, h);
                else
                    quant16(w, g_qw, g_sw, N_DIM, rowc - M_DIM, kb, h);
            }
            __syncthreads();
            if (tid == 0) {
                __threadfence();
                atomicAdd(&g_sync[s], 1);
            }
        }
    } else {
        if (tid == 0) {
            #pragma unroll
            for (int s = 0; s < NFLAGS; s++) atomicAdd(&g_sync[s], 1);
        }
    }

    // ================= Phase 2: persistent GEMM =================
    const int wid  = tid >> 5;
    const int lane = tid & 31;
    const int m0   = (wid >> 1) * 32;
    const int n0   = (wid & 1) * 32;

    // tile-invariant loader geometry
    int ldRow[4], ldK16[4];
    uint32_t dA[4], dB[4];
    #pragma unroll
    for (int i = 0; i < 4; i++) {
        int c = tid + i * THREADS;              // 0..511
        ldRow[i] = c >> 3;
        ldK16[i] = c & 7;
        uint32_t d = swz128(ldRow[i] * 128 + ldK16[i] * 16);
        dA[i] = A_OFF + d;
        dB[i] = B_OFF + d;
    }
    const int sHalf = tid >> 6;                 // 0 = sx, 1 = sw
    const int sKbl  = (tid & 63) >> 4;
    const int sQq   = tid & 15;
    const uint32_t dS = (sHalf == 0 ? SX_OFF : SW_OFF) + sKbl * 256 + sQq * 16;
    const size_t sAdv = (size_t)4 * (sHalf == 0 ? M_DIM : N_DIM) * sizeof(float);

    // tile-invariant ldsm offsets
    const int r       = lane & 7;
    const int sel     = lane >> 3;
    const int selRow  = (sel & 1) * 8;
    const int selByte = (sel >> 1) * 16;
    const int qrow    = lane >> 2;
    const int qcol    = (lane & 3) * 2;

    uint32_t offA[4][2], offB[4][2];
    #pragma unroll
    for (int kb = 0; kb < 4; kb++) {
        const int kbyte = kb * 32 + selByte;
        #pragma unroll
        for (int tm = 0; tm < 2; tm++)
            offA[kb][tm] = A_OFF +
                swz128((m0 + tm * 16 + r + selRow) * 128 + kbyte);
        #pragma unroll
        for (int g = 0; g < 2; g++)
            offB[kb][g] = B_OFF +
                swz128((n0 + g * 16 + r + selRow) * 128 + kbyte);
    }
    const int sxBase = (m0 + qrow) * 4;
    const int swBase = (n0 + qcol) * 4;

    int f_done = -1;

    for (;;) {
        if (tid == 0) s_tile = atomicAdd(&g_sync[NFLAGS], 1);
        CP_WAIT(0);                 // drain pipeline before buffer reuse
        __syncthreads();
        const int tile = s_tile;
        if (tile >= NTILES) break;

        const int bm0 = (tile >> 6) * BM;
        const int bn0 = (tile & 63) * BN;

        // per-tile loader pointers
        const uint8_t* pA[4];
        const uint8_t* pB[4];
        #pragma unroll
        for (int i = 0; i < 4; i++) {
            pA[i] = g_qx + (size_t)(bm0 + ldRow[i]) * K_DIM + ldK16[i] * 16;
            pB[i] = g_qw + (size_t)(bn0 + ldRow[i]) * K_DIM + ldK16[i] * 16;
        }
        const float* pS;
        if (sHalf == 0)
            pS = g_sx + (size_t)sKbl * M_DIM + bm0 + sQq * 4;
        else
            pS = g_sw + (size_t)sKbl * N_DIM + bn0 + sQq * 4;

        auto load_stage = [&](int buf) {
            const uint32_t st = sb + buf * STAGE_B;
            #pragma unroll
            for (int i = 0; i < 4; i++) {
                CP_ASYNC16(st + dA[i], pA[i]);  pA[i] += BK;
            }
            #pragma unroll
            for (int i = 0; i < 4; i++) {
                CP_ASYNC16(st + dB[i], pB[i]);  pB[i] += BK;
            }
            CP_ASYNC16(st + dS, pS);
            pS = (const float*)((const char*)pS + sAdv);
        };
        auto wait_flag = [&](int f) {
            if (f > f_done) {
                if (tid == 0)
                    while (atomicAdd(&g_sync[f], 0) != narrive) __nanosleep(64);
                __syncthreads();
                f_done = f;
            }
        };

        unsigned long long acc2[2][4][2];
        #pragma unroll
        for (int i = 0; i < 2; i++)
            #pragma unroll
            for (int j = 0; j < 4; j++) {
                acc2[i][j][0] = 0ull; acc2[i][j][1] = 0ull;
            }

        wait_flag(0);               // covers GEMM stages 0..3
        #pragma unroll
        for (int s = 0; s < STAGES - 1; s++) {
            load_stage(s);
            CP_COMMIT();
        }

        for (int it = 0; it < NITER; it++) {
            CP_WAIT(STAGES - 2);
            __syncthreads();

            const int ns = it + STAGES - 1;
            if (ns < NITER) {
                wait_flag(ns >> 2);
                load_stage(ns & (STAGES - 1));
            }
            CP_COMMIT();

            const int buf = it & (STAGES - 1);
            const uint32_t su = sb + buf * STAGE_B;
            const char* sxS = smem + buf * STAGE_B + SX_OFF;
            const char* swS = smem + buf * STAGE_B + SW_OFF;

            // whole-stage fragment prefetch: 16 ldsm back-to-back
            uint32_t a[4][2][4], b[4][2][4];
            #pragma unroll
            for (int kb = 0; kb < 4; kb++) {
                LDSM4(a[kb][0][0], a[kb][0][1], a[kb][0][2], a[kb][0][3],
                      su + offA[kb][0]);
                LDSM4(a[kb][1][0], a[kb][1][1], a[kb][1][2], a[kb][1][3],
                      su + offA[kb][1]);
                LDSM4(b[kb][0][0], b[kb][0][1], b[kb][0][2], b[kb][0][3],
                      su + offB[kb][0]);
                LDSM4(b[kb][1][0], b[kb][1][1], b[kb][1][2], b[kb][1][3],
                      su + offB[kb][1]);
            }

            #pragma unroll
            for (int kb = 0; kb < 4; kb++) {
                unsigned long long sxd[2][2];
                #pragma unroll
                for (int tm = 0; tm < 2; tm++)
                    #pragma unroll
                    for (int h = 0; h < 2; h++) {
                        float sx = *(const float*)(sxS + kb * 256 + sxBase +
                                                   tm * 64 + h * 32);
                        sxd[tm][h] = pk2(sx, sx);
                    }
                unsigned long long swp[4];
                #pragma unroll
                for (int tn = 0; tn < 4; tn++)
                    swp[tn] = *(const unsigned long long*)(swS + kb * 256 +
                                                           swBase + tn * 32);

                #pragma unroll
                for (int tm = 0; tm < 2; tm++)
                    #pragma unroll
                    for (int g = 0; g < 2; g++) {
                        float p[4], q[4];
                        MMA_FP8_Z(p, a[kb][tm], b[kb][g][0], b[kb][g][2]);
                        MMA_FP8_Z(q, a[kb][tm], b[kb][g][1], b[kb][g][3]);
                        const int t0 = 2 * g, t1 = 2 * g + 1;
                        pfma2(acc2[tm][t0][0], pk2(p[0], p[1]),
                              pmul2(sxd[tm][0], swp[t0]));
                        pfma2(acc2[tm][t0][1], pk2(p[2], p[3]),
                              pmul2(sxd[tm][1], swp[t0]));
                        pfma2(acc2[tm][t1][0], pk2(q[0], q[1]),
                              pmul2(sxd[tm][0], swp[t1]));
                        pfma2(acc2[tm][t1][1], pk2(q[2], q[3]),
                              pmul2(sxd[tm][1], swp[t1]));
                    }
            }
        }

        // epilogue: 8-byte packed stores
        #pragma unroll
        for (int tm = 0; tm < 2; tm++)
            #pragma unroll
            for (int h = 0; h < 2; h++) {
                int row = bm0 + m0 + tm * 16 + qrow + 8 * h;
                #pragma unroll
                for (int tn = 0; tn < 4; tn++) {
                    unsigned long long v = acc2[tm][tn][h];
                    *(unsigned long long*)(C + (size_t)row * N_DIM +
                                           bn0 + n0 + tn * 8 + qcol) = v;
                }
            }
    }
}

// ---------------------------------------------------------------------------
extern "C" void kernel_launch(void* const* d_in, const int* in_sizes, int n_in,
                              void* d_out, int out_size) {
    (void)n_in; (void)in_sizes; (void)out_size;
    const float* x = (const float*)d_in[0];   // [M, K]
    const float* w = (const float*)d_in[1];   // [N, K]
    float* out = (float*)d_out;               // [M, N]

    // reset flags + tile counter (memset node; graph-capturable, no alloc)
    void* syncp = nullptr;
    cudaGetSymbolAddress(&syncp, g_sync);
    cudaMemsetAsync(syncp, 0, sizeof(int) * (NFLAGS + 1));

    int dev = 0, nsm = 148;
    cudaGetDevice(&dev);
    cudaDeviceGetAttribute(&nsm, cudaDevAttrMultiProcessorCount, dev);
    const int grid = 3 * nsm;                 // exactly one resident wave

    cudaFuncSetAttribute(fused_kernel,
                         cudaFuncAttributeMaxDynamicSharedMemorySize,
                         SMEM_TOTAL);
    fused_kernel<<<grid, THREADS, SMEM_TOTAL>>>(x, w, out);
}

// round 14
// speedup vs baseline: 1.0191x; 1.0191x over previous
#include <cuda_runtime.h>
#include <cuda_bf16.h>
#include <cstdint>

// Problem dims (fixed)
#define M_DIM 1024
#define K_DIM 4096
#define N_DIM 4096
#define QBLK  32
#define NKB   (K_DIM / QBLK)      // 128

// GEMM tiling: 64x64 CTA, 4 warps of 32x32, STAGES=4, 3 CTAs/SM
#define BM 64
#define BN 64
#define BK 128                    // 128 fp8 = 128B rows (SW128), 4 quant blocks
#define STAGES 4
#define NITER (K_DIM / BK)        // 32
#define THREADS 128

// Stage smem: A(8K) | B(8K)  (scales now come via LDG, not smem)
#define A_OFF   0
#define B_OFF   8192
#define STAGE_B 16384
#define SMEM_TOTAL (STAGES * STAGE_B)   // 65536 -> 3 CTAs/SM

// Scratch (device globals)
__device__ uint8_t g_qx[(size_t)M_DIM * K_DIM];      // 4 MB  (e4m3 palette)
__device__ uint8_t g_qw[(size_t)N_DIM * K_DIM];      // 16 MB (e4m3 palette)
__device__ float   g_sx2[(size_t)NKB * M_DIM * 2];   // [kb][m][2] SPLATTED
__device__ float   g_sw[(size_t)NKB * N_DIM];        // [kb][n]

// ---------------------------------------------------------------------------
// PTX helpers
// ---------------------------------------------------------------------------
__device__ __forceinline__ uint32_t smem_u32(const void* p) {
    uint32_t a;
    asm("{ .reg .u64 t; cvta.to.shared.u64 t, %1; cvt.u32.u64 %0, t; }"
        : "=r"(a) : "l"(p));
    return a;
}
#define CP_ASYNC16(dst, src) \
    asm volatile("cp.async.cg.shared.global [%0], [%1], 16;" \
                 :: "r"(dst), "l"(src) : "memory")
#define CP_COMMIT() asm volatile("cp.async.commit_group;" ::: "memory")
#define CP_WAIT(n)  asm volatile("cp.async.wait_group %0;" :: "n"(n) : "memory")

#define LDSM4(r0, r1, r2, r3, addr) \
    asm volatile("ldmatrix.sync.aligned.m8n8.x4.shared.b16 {%0,%1,%2,%3}, [%4];" \
                 : "=r"(r0), "=r"(r1), "=r"(r2), "=r"(r3) : "r"(addr))

// fp8 e4m3 MMA (K=32, fp32 accum, C=0) with outputs packed to two f32x2
// pairs INSIDE one asm block — lets ptxas allocate p0..p3 as aligned pairs
// and elide the movs.
__device__ __forceinline__ void mma_fp8_pk(unsigned long long& d01,
                                           unsigned long long& d23,
                                           const uint32_t* a,
                                           uint32_t b0, uint32_t b1) {
    asm volatile(
        "{ .reg .f32 p0, p1, p2, p3;\n\t"
        "mma.sync.aligned.m16n8k32.row.col.f32.e4m3.e4m3.f32 "
        "{p0,p1,p2,p3},{%2,%3,%4,%5},{%6,%7},{%8,%8,%8,%8};\n\t"
        "mov.b64 %0, {p0,p1};\n\t"
        "mov.b64 %1, {p2,p3}; }"
        : "=l"(d01), "=l"(d23)
        : "r"(a[0]), "r"(a[1]), "r"(a[2]), "r"(a[3]),
          "r"(b0), "r"(b1), "f"(0.0f));
}

// packed f32x2 ops
__device__ __forceinline__ unsigned long long pmul2(unsigned long long a,
                                                    unsigned long long b) {
    unsigned long long d;
    asm("mul.rn.f32x2 %0, %1, %2;" : "=l"(d) : "l"(a), "l"(b));
    return d;
}
__device__ __forceinline__ void pfma2(unsigned long long& acc,
                                      unsigned long long a,
                                      unsigned long long b) {
    asm("fma.rn.f32x2 %0, %1, %2, %0;" : "+l"(acc) : "l"(a), "l"(b));
}

__device__ __forceinline__ uint32_t swz128(uint32_t off) {
    return off ^ ((off >> 3) & 0x70);
}

// ---------------------------------------------------------------------------
// Quantize (fused, one launch): ceil-based EXACT snap (argmin tie-to-lower).
// x scales written SPLATTED (2 copies) for direct LDG.64 f32x2 operands.
// ---------------------------------------------------------------------------
__device__ __forceinline__ float snap1(float v, float r6) {
    float su = fabsf(v) * r6;
    float pl = ceilf(fmaf(su, 2.0f, -0.5f)) * 0.5f;
    float ph = fminf(ceilf(su - 0.5f), 4.0f);
    float p  = su < 2.0f ? pl : ph;
    p = su > 5.0f ? 6.0f : p;
    return copysignf(p, v);
}
__device__ __forceinline__ uint32_t pack4_e4m3(const float4 v, float r6) {
    uint16_t lo, hi;
    float a0 = snap1(v.x, r6), a1 = snap1(v.y, r6);
    float a2 = snap1(v.z, r6), a3 = snap1(v.w, r6);
    asm("cvt.rn.satfinite.e4m3x2.f32 %0, %1, %2;" : "=h"(lo) : "f"(a1), "f"(a0));
    asm("cvt.rn.satfinite.e4m3x2.f32 %0, %1, %2;" : "=h"(hi) : "f"(a3), "f"(a2));
    return (uint32_t)lo | ((uint32_t)hi << 16);
}

#define XTHREADS ((M_DIM * (size_t)K_DIM) / 16)   // 262144

__global__ __launch_bounds__(256)
void quant_fused_kernel(const float* __restrict__ x,
                        const float* __restrict__ w,
                        uint8_t* __restrict__ qx,
                        uint8_t* __restrict__ qw,
                        float* __restrict__ sx2,
                        float* __restrict__ sw) {
    const size_t gt = blockIdx.x * 256 + threadIdx.x;

    const float* src;
    uint8_t* dst;
    size_t e0;
    bool isx;
    if (gt < XTHREADS) {
        src = x;  dst = qx;  e0 = gt * 16;              isx = true;
    } else {
        src = w;  dst = qw;  e0 = (gt - XTHREADS) * 16; isx = false;
    }

    float4 v[4];
    #pragma unroll
    for (int i = 0; i < 4; i++) v[i] = *(const float4*)(src + e0 + i * 4);

    float a = 0.0f;
    #pragma unroll
    for (int i = 0; i < 4; i++)
        a = fmaxf(a, fmaxf(fmaxf(fabsf(v[i].x), fabsf(v[i].y)),
                           fmaxf(fabsf(v[i].z), fabsf(v[i].w))));
    a = fmaxf(a, __shfl_xor_sync(0xffffffffu, a, 1));
    float bm = fmaxf(a, 1e-12f);
    float r6 = 6.0f / bm;

    uint4 pk;
    pk.x = pack4_e4m3(v[0], r6);
    pk.y = pack4_e4m3(v[1], r6);
    pk.z = pack4_e4m3(v[2], r6);
    pk.w = pack4_e4m3(v[3], r6);
    *(uint4*)(dst + e0) = pk;

    if ((threadIdx.x & 1) == 0) {
        int row = (int)(e0 / K_DIM);
        int kb  = (int)((e0 % K_DIM) / QBLK);
        float s = bm / 6.0f;
        if (isx) {
            float2 ss = make_float2(s, s);
            *(float2*)(sx2 + ((size_t)kb * M_DIM + row) * 2) = ss;
        } else {
            sw[(size_t)kb * N_DIM + row] = s;
        }
    }
}

// ---------------------------------------------------------------------------
// FP8 block-scaled GEMM: 64x64 CTA, 4 warps of 32x32, STAGES=4, 3 CTAs/SM.
// Scales via L1-cached LDG (immediate offsets); fused MMA+pack asm.
// C[m,n] = sum_kb MMA_k32(qx,qw) * sx[m,kb]*sw[n,kb]
// ---------------------------------------------------------------------------
__global__ __launch_bounds__(THREADS, 3)
void gemm_fp8(const uint8_t* __restrict__ A,   // [M,K] e4m3
              const uint8_t* __restrict__ B,   // [N,K] e4m3
              const float* __restrict__ SX2,   // [NKB][M][2] splatted
              const float* __restrict__ SW,    // [NKB][N]
              float* __restrict__ C) {
    extern __shared__ __align__(1024) char smem[];
    const uint32_t sb = smem_u32(smem);
    const int tid  = threadIdx.x;
    const int wid  = tid >> 5;
    const int lane = tid & 31;
    const int m0   = (wid >> 1) * 32;
    const int n0   = (wid & 1) * 32;
    const int bm0  = blockIdx.y * BM;
    const int bn0  = blockIdx.x * BN;

    // ---- hoisted loader state: 8 tile pointers + dst offsets ----
    const uint8_t* pA[4];
    const uint8_t* pB[4];
    uint32_t dA[4], dB[4];
    #pragma unroll
    for (int i = 0; i < 4; i++) {
        int c = tid + i * THREADS;              // 0..511
        int row = c >> 3, k16 = c & 7;
        pA[i] = A + (size_t)(bm0 + row) * K_DIM + k16 * 16;
        pB[i] = B + (size_t)(bn0 + row) * K_DIM + k16 * 16;
        uint32_t d = swz128(row * 128 + k16 * 16);
        dA[i] = A_OFF + d;
        dB[i] = B_OFF + d;
    }

    auto load_stage = [&](int buf) {
        const uint32_t st = sb + buf * STAGE_B;
        #pragma unroll
        for (int i = 0; i < 4; i++) {
            CP_ASYNC16(st + dA[i], pA[i]);  pA[i] += BK;
        }
        #pragma unroll
        for (int i = 0; i < 4; i++) {
            CP_ASYNC16(st + dB[i], pB[i]);  pB[i] += BK;
        }
    };

    // packed fp32 accumulators: acc2[tm][tn][h] = (c_even, c_odd)
    unsigned long long acc2[2][4][2];
    #pragma unroll
    for (int i = 0; i < 2; i++)
        #pragma unroll
        for (int j = 0; j < 4; j++) {
            acc2[i][j][0] = 0ull; acc2[i][j][1] = 0ull;
        }

    #pragma unroll
    for (int s = 0; s < STAGES - 1; s++) {
        load_stage(s);
        CP_COMMIT();
    }

    // hoisted ldsm offsets
    const int r       = lane & 7;
    const int sel     = lane >> 3;
    const int selRow  = (sel & 1) * 8;
    const int selByte = (sel >> 1) * 16;
    const int qrow    = lane >> 2;   // 0..7
    const int qcol    = (lane & 3) * 2;

    uint32_t offA[4][2], offB[4][2];
    #pragma unroll
    for (int kb = 0; kb < 4; kb++) {
        const int kbyte = kb * 32 + selByte;
        #pragma unroll
        for (int tm = 0; tm < 2; tm++)
            offA[kb][tm] = A_OFF +
                swz128((m0 + tm * 16 + r + selRow) * 128 + kbyte);
        #pragma unroll
        for (int g = 0; g < 2; g++)
            offB[kb][g] = B_OFF +
                swz128((n0 + g * 16 + r + selRow) * 128 + kbyte);
    }

    // per-warp scale pointers (advanced once per iteration; all other
    // addressing is compile-time immediate offsets)
    const float* sxp = SX2 + (size_t)(bm0 + m0 + qrow) * 2;   // + kb*2M + tm*32 + h*16
    const float* swp_ = SW + (bn0 + n0 + qcol);               // + kb*N + tn*8

    for (int it = 0; it < NITER; it++) {
        CP_WAIT(STAGES - 2);
        __syncthreads();

        if (it + STAGES - 1 < NITER)
            load_stage((it + STAGES - 1) & (STAGES - 1));
        CP_COMMIT();

        const int buf = it & (STAGES - 1);
        const uint32_t su = sb + buf * STAGE_B;

        // whole-stage fragment prefetch: 16 ldsm back-to-back
        uint32_t a[4][2][4], b[4][2][4];
        #pragma unroll
        for (int kb = 0; kb < 4; kb++) {
            LDSM4(a[kb][0][0], a[kb][0][1], a[kb][0][2], a[kb][0][3],
                  su + offA[kb][0]);
            LDSM4(a[kb][1][0], a[kb][1][1], a[kb][1][2], a[kb][1][3],
                  su + offA[kb][1]);
            LDSM4(b[kb][0][0], b[kb][0][1], b[kb][0][2], b[kb][0][3],
                  su + offB[kb][0]);
            LDSM4(b[kb][1][0], b[kb][1][1], b[kb][1][2], b[kb][1][3],
                  su + offB[kb][1]);
        }

        #pragma unroll
        for (int kb = 0; kb < 4; kb++) {
            // scale operands: direct LDG.64 (L1-cached), immediate offsets
            unsigned long long sxd[2][2], swv[4];
            #pragma unroll
            for (int tm = 0; tm < 2; tm++)
                #pragma unroll
                for (int h = 0; h < 2; h++)
                    sxd[tm][h] = *(const unsigned long long*)
                        (sxp + (size_t)kb * 2 * M_DIM + tm * 32 + h * 16);
            #pragma unroll
            for (int tn = 0; tn < 4; tn++)
                swv[tn] = *(const unsigned long long*)
                    (swp_ + (size_t)kb * N_DIM + tn * 8);

            #pragma unroll
            for (int tm = 0; tm < 2; tm++)
                #pragma unroll
                for (int g = 0; g < 2; g++) {
                    unsigned long long p01, p23, q01, q23;
                    mma_fp8_pk(p01, p23, a[kb][tm], b[kb][g][0], b[kb][g][2]);
                    mma_fp8_pk(q01, q23, a[kb][tm], b[kb][g][1], b[kb][g][3]);
                    const int t0 = 2 * g, t1 = 2 * g + 1;
                    pfma2(acc2[tm][t0][0], p01, pmul2(sxd[tm][0], swv[t0]));
                    pfma2(acc2[tm][t0][1], p23, pmul2(sxd[tm][1], swv[t0]));
                    pfma2(acc2[tm][t1][0], q01, pmul2(sxd[tm][0], swv[t1]));
                    pfma2(acc2[tm][t1][1], q23, pmul2(sxd[tm][1], swv[t1]));
                }
        }

        // advance scale pointers by 4 quant blocks
        sxp  += (size_t)4 * 2 * M_DIM;
        swp_ += (size_t)4 * N_DIM;
    }

    // epilogue: 8-byte packed stores
    #pragma unroll
    for (int tm = 0; tm < 2; tm++)
        #pragma unroll
        for (int h = 0; h < 2; h++) {
            int row = bm0 + m0 + tm * 16 + qrow + 8 * h;
            #pragma unroll
            for (int tn = 0; tn < 4; tn++) {
                unsigned long long v = acc2[tm][tn][h];
                *(unsigned long long*)(C + (size_t)row * N_DIM +
                                       bn0 + n0 + tn * 8 + qcol) = v;
            }
        }
}

// ---------------------------------------------------------------------------
extern "C" void kernel_launch(void* const* d_in, const int* in_sizes, int n_in,
                              void* d_out, int out_size) {
    (void)n_in; (void)in_sizes; (void)out_size;
    const float* x = (const float*)d_in[0];   // [M, K]
    const float* w = (const float*)d_in[1];   // [N, K]
    float* out = (float*)d_out;               // [M, N]

    uint8_t *qx = nullptr, *qw = nullptr;
    float *sx2 = nullptr, *sw = nullptr;
    cudaGetSymbolAddress((void**)&qx, g_qx);
    cudaGetSymbolAddress((void**)&qw, g_qw);
    cudaGetSymbolAddress((void**)&sx2, g_sx2);
    cudaGetSymbolAddress((void**)&sw, g_sw);

    // fused quant: x (1024 CTAs) + w (4096 CTAs) in one launch
    const int total_ctas = (int)(((M_DIM + N_DIM) * (size_t)K_DIM) / 16 / 256);
    quant_fused_kernel<<<total_ctas, 256>>>(x, w, qx, qw, sx2, sw);

    cudaFuncSetAttribute(gemm_fp8,
                         cudaFuncAttributeMaxDynamicSharedMemorySize,
                         SMEM_TOTAL);
    dim3 grid(N_DIM / BN, M_DIM / BM);        // (64, 16) = 1024 CTAs
    gemm_fp8<<<grid, THREADS, SMEM_TOTAL>>>(qx, qw, sx2, sw, out);
}